// round 11
// baseline (speedup 1.0000x reference)
#include <cuda_runtime.h>
#include <cmath>
#include <cstdint>

// ---------------- problem constants ----------------
#define B_    64
#define S_    32
#define INF_  512
#define N1_   1229
#define N2_   819
#define N3_   512
#define NU_   2560
#define K1_   1741
#define K2_   2048
#define K3_   1331
#define NHP1_ 1248
#define NHP2_ 832
#define NHP3_ 512
#define NC1_  4992
#define NC2_  3328
#define NC3_  2048
#define T1_   39
#define T2_   26
#define T3_   16
#define C1_   28
#define C2_   32
#define C3_   21
#define H1P_  1280
#define Z2P_  2048
#define Z3P_  1344
#define KS1_  3
#define KS2_  5
#define KS3_  9
#define NBLK_ 148
#define NTHR_ 256

#define QSCL_ 32639.0f
#define XB_   6.0f            // compile-time |x| bound (x ~ N(0,1), max ~5.3; clamped gracefully)

// smem per buffer: Whi[128x80] Wlo[128x80] Zhi[64x80] Zlo[64x80]
#define WPL_   10240
#define ZPL_   5120
#define QBUF_  30720
#define SMEMQ_ (2 * QBUF_ + 128)

// ---------------- device scratch ----------------
__device__ int8_t g_W1qh[(size_t)T1_ * C1_ * 8192];
__device__ int8_t g_W1ql[(size_t)T1_ * C1_ * 8192];
__device__ int8_t g_W2qh[(size_t)T2_ * C2_ * 8192];
__device__ int8_t g_W2ql[(size_t)T2_ * C2_ * 8192];
__device__ int8_t g_W3qh[(size_t)T3_ * C3_ * 8192];
__device__ int8_t g_W3ql[(size_t)T3_ * C3_ * 8192];
__device__ float  g_swq1[NC1_], g_swi1[NC1_];
__device__ float  g_swq2[NC2_], g_swi2[NC2_];
__device__ float  g_swq3[NC3_], g_swi3[NC3_];
__device__ int8_t g_Xqh[(size_t)S_ * B_ * INF_], g_Xql[(size_t)S_ * B_ * INF_];
__device__ int8_t g_H1qh[B_ * H1P_], g_H1ql[B_ * H1P_];
__device__ int8_t g_Z2qh[B_ * Z2P_], g_Z2ql[B_ * Z2P_];
__device__ int8_t g_Z3qh[B_ * Z3P_], g_Z3ql[B_ * Z3P_];
__device__ float  g_P1[(size_t)KS1_ * B_ * NC1_];
__device__ float  g_P2[(size_t)KS2_ * B_ * NC2_];
__device__ float  g_P3[(size_t)KS3_ * B_ * NC3_];
__device__ float  g_H1f[B_ * N1_], g_H2f[B_ * N2_], g_H3f[B_ * N3_];
__device__ unsigned g_bar_cnt;
__device__ volatile unsigned g_bar_epoch;

// ---------------- asm helpers ----------------
#define CP16(dst, src)  asm volatile("cp.async.ca.shared.global [%0], [%1], 16;" :: "r"(dst), "l"(src))
#define CPCOMMIT()      asm volatile("cp.async.commit_group;")
#define CPWAIT0()       asm volatile("cp.async.wait_group 0;")
#define CPWAIT1()       asm volatile("cp.async.wait_group 1;")

#define LDX4(r, addr) \
    asm volatile("ldmatrix.sync.aligned.m8n8.x4.shared.b16 {%0,%1,%2,%3}, [%4];" \
        : "=r"((r)[0]), "=r"((r)[1]), "=r"((r)[2]), "=r"((r)[3]) : "r"(addr))

__device__ __forceinline__ void imma(int* c, const unsigned* a, unsigned b0, unsigned b1) {
    asm volatile("mma.sync.aligned.m16n8k32.row.col.s32.s8.s8.s32 "
                 "{%0,%1,%2,%3}, {%4,%5,%6,%7}, {%8,%9}, {%0,%1,%2,%3};"
                 : "+r"(c[0]), "+r"(c[1]), "+r"(c[2]), "+r"(c[3])
                 : "r"(a[0]), "r"(a[1]), "r"(a[2]), "r"(a[3]), "r"(b0), "r"(b1));
}

__device__ __forceinline__ void grid_barrier() {
    __threadfence();
    __syncthreads();
    if (threadIdx.x == 0) {
        unsigned e = g_bar_epoch;
        if (atomicAdd(&g_bar_cnt, 1u) == gridDim.x - 1u) {
            g_bar_cnt = 0u;
            __threadfence();
            g_bar_epoch = e + 1u;
        } else {
            while (g_bar_epoch == e) { }
        }
    }
    __syncthreads();
}

__device__ __forceinline__ void q_split(float v, float s, int8_t& hi, int8_t& lo) {
    float q = rintf(v * s);
    q = fminf(fmaxf(q, -QSCL_), QSCL_);
    int z = (int)q;
    int l = ((z + 128) & 255) - 128;
    hi = (int8_t)((z - l) >> 8);
    lo = (int8_t)l;
}

// ================= prepA: row scales + x quant + h0 init =================
#define PA_W_  1296
#define PA_X_  1024
#define PA_H_  64

__global__ __launch_bounds__(NTHR_) void k_prepA(
    const float* __restrict__ x, const float* __restrict__ h0,
    const float* __restrict__ Wg1, const float* __restrict__ Wh1,
    const float* __restrict__ Wfg1, const float* __restrict__ Wfh1, const float* __restrict__ M1,
    const float* __restrict__ Wg2, const float* __restrict__ Wh2,
    const float* __restrict__ Wfg2, const float* __restrict__ Wfh2, const float* __restrict__ M2,
    const float* __restrict__ Wg3, const float* __restrict__ Wh3,
    const float* __restrict__ Wfg3, const float* __restrict__ Wfh3, const float* __restrict__ M3) {
    int bid = blockIdx.x, tid = threadIdx.x;
    if (bid < PA_W_) {
        int gw = bid * 8 + (tid >> 5), lane = tid & 31;
        const float *Wg, *Wh, *Wfg, *Wfh, *Msk;
        float *swq, *swi;
        int Nh, K, Nhp, pr, cell;
        if (gw < NC1_)             { cell = 0; pr = gw; }
        else if (gw < NC1_ + NC2_) { cell = 1; pr = gw - NC1_; }
        else                       { cell = 2; pr = gw - NC1_ - NC2_; }
        if (cell == 0) { Wg=Wg1; Wh=Wh1; Wfg=Wfg1; Wfh=Wfh1; Msk=M1; swq=g_swq1; swi=g_swi1; Nh=N1_; K=K1_; Nhp=NHP1_; }
        else if (cell == 1) { Wg=Wg2; Wh=Wh2; Wfg=Wfg2; Wfh=Wfh2; Msk=M2; swq=g_swq2; swi=g_swi2; Nh=N2_; K=K2_; Nhp=NHP2_; }
        else { Wg=Wg3; Wh=Wh3; Wfg=Wfg3; Wfh=Wfh3; Msk=M3; swq=g_swq3; swi=g_swi3; Nh=N3_; K=K3_; Nhp=NHP3_; }
        int hd = pr / Nhp, n = pr - hd * Nhp;
        float mx = 0.f;
        if (n < Nh) {
            const float* W = (hd == 0) ? Wg : (hd == 1) ? Wh : (hd == 2) ? Wfg : Wfh;
            for (int k = lane; k < K; k += 32) {
                float f = (cell == 0 && k < INF_) ? XB_ : 1.f;
                mx = fmaxf(mx, fabsf(W[(size_t)n * K + k] * Msk[(size_t)n * K + k] * f));
            }
        }
#pragma unroll
        for (int s = 16; s > 0; s >>= 1) mx = fmaxf(mx, __shfl_xor_sync(0xFFFFFFFFu, mx, s));
        if (lane == 0) {
            if (mx > 0.f) { swq[pr] = QSCL_ / mx; swi[pr] = mx / (QSCL_ * QSCL_); }
            else          { swq[pr] = 0.f;        swi[pr] = 0.f; }
        }
    } else if (bid < PA_W_ + PA_X_) {
        // x quantize: planes [t][b][f] from x[(b*S+t)*512+f], scale QSCL_/XB_
        const float sx = QSCL_ / XB_;
        for (int i = (bid - PA_W_) * NTHR_ + tid; i < S_ * B_ * INF_; i += PA_X_ * NTHR_) {
            int f = i & 511, b = (i >> 9) & 63, t = i >> 15;
            float v = x[((size_t)b * S_ + t) * INF_ + f];
            int8_t hi, lo;
            q_split(v, sx, hi, lo);
            g_Xqh[i] = hi; g_Xql[i] = lo;
        }
    } else {
        int base = (bid - PA_W_ - PA_X_) * NTHR_ + tid;
        int stride = PA_H_ * NTHR_;
        for (int i = base; i < B_ * NU_; i += stride) {
            int m = i / NU_, c = i - m * NU_;
            float v = h0[i];
            int8_t hi, lo;
            q_split(v, QSCL_, hi, lo);
            if (c < N1_) {
                g_H1f[m * N1_ + c] = v;
                g_H1qh[m * H1P_ + c] = hi; g_H1ql[m * H1P_ + c] = lo;
            } else if (c < N1_ + N2_) {
                int cc = c - N1_;
                g_H2f[m * N2_ + cc] = v;
                g_Z2qh[m * Z2P_ + N1_ + cc] = hi; g_Z2ql[m * Z2P_ + N1_ + cc] = lo;
            } else {
                int cc = c - N1_ - N2_;
                g_H3f[m * N3_ + cc] = v;
                g_Z3qh[m * Z3P_ + N2_ + cc] = hi; g_Z3ql[m * Z3P_ + N2_ + cc] = lo;
            }
        }
        for (int i = base; i < B_ * (H1P_ - N1_); i += stride) {
            int m = i / (H1P_ - N1_), c = N1_ + (i - m * (H1P_ - N1_));
            g_H1qh[m * H1P_ + c] = 0; g_H1ql[m * H1P_ + c] = 0;
        }
        for (int i = base; i < B_ * (Z3P_ - K3_); i += stride) {
            int m = i / (Z3P_ - K3_), c = K3_ + (i - m * (Z3P_ - K3_));
            g_Z3qh[m * Z3P_ + c] = 0; g_Z3ql[m * Z3P_ + c] = 0;
        }
    }
}

// ================= prepB: weight quantize (needs swq) =================
__global__ __launch_bounds__(NTHR_) void k_prepB(
    const float* __restrict__ Wg1, const float* __restrict__ Wh1,
    const float* __restrict__ Wfg1, const float* __restrict__ Wfh1, const float* __restrict__ M1,
    const float* __restrict__ Wg2, const float* __restrict__ Wh2,
    const float* __restrict__ Wfg2, const float* __restrict__ Wfh2, const float* __restrict__ M2,
    const float* __restrict__ Wg3, const float* __restrict__ Wh3,
    const float* __restrict__ Wfg3, const float* __restrict__ Wfh3, const float* __restrict__ M3) {
    const int NW1 = T1_ * C1_, NW2 = T2_ * C2_;
    int bid = blockIdx.x, tid = threadIdx.x;
    const float *Wg, *Wh, *Wfg, *Wfh, *Msk, *swq;
    int8_t *Dh, *Dl;
    int Nh, K, Nhp, nch, blk, cell;
    if (bid < NW1) { cell=0; blk=bid; Wg=Wg1; Wh=Wh1; Wfg=Wfg1; Wfh=Wfh1; Msk=M1; swq=g_swq1; Dh=g_W1qh; Dl=g_W1ql; Nh=N1_; K=K1_; Nhp=NHP1_; nch=C1_; }
    else if (bid < NW1 + NW2) { cell=1; blk=bid-NW1; Wg=Wg2; Wh=Wh2; Wfg=Wfg2; Wfh=Wfh2; Msk=M2; swq=g_swq2; Dh=g_W2qh; Dl=g_W2ql; Nh=N2_; K=K2_; Nhp=NHP2_; nch=C2_; }
    else { cell=2; blk=bid-NW1-NW2; Wg=Wg3; Wh=Wh3; Wfg=Wfg3; Wfh=Wfh3; Msk=M3; swq=g_swq3; Dh=g_W3qh; Dl=g_W3ql; Nh=N3_; K=K3_; Nhp=NHP3_; nch=C3_; }
    int tile = blk / nch, chunk = blk - tile * nch;
    size_t base = (size_t)blk * 8192;
    for (int e = tid; e < 8192; e += NTHR_) {
        int row = e >> 6, col = e & 63;
        int pn = tile * 128 + row;
        int hd = pn / Nhp, n = pn - hd * Nhp;
        int k = chunk * 64 + col;
        float v = 0.f;
        if (n < Nh && k < K) {
            const float* W = (hd == 0) ? Wg : (hd == 1) ? Wh : (hd == 2) ? Wfg : Wfh;
            float f = (cell == 0 && k < INF_) ? XB_ : 1.f;
            v = W[(size_t)n * K + k] * Msk[(size_t)n * K + k] * f;
        }
        int8_t hi, lo;
        q_split(v, swq[pn], hi, lo);
        Dh[base + e] = hi; Dl[base + e] = lo;
    }
}

// ================= int8 GEMM phase =================
__device__ __forceinline__ void stage_q(uint32_t sb,
        const int8_t* __restrict__ Wqh, const int8_t* __restrict__ Wql, size_t wbase,
        const int8_t* __restrict__ zh, const int8_t* __restrict__ zl,
        int zstride, int colbase) {
    int tid = threadIdx.x;
#pragma unroll
    for (int i = 0; i < 4; i++) {       // A: 16KB (2 planes x 128 x 64)
        int e = tid + i * 256;
        int pl = e >> 9, r = (e >> 2) & 127, sg = e & 3;
        const char* g = (const char*)((pl ? Wql : Wqh) + wbase) + r * 64 + sg * 16;
        CP16(sb + pl * WPL_ + r * 80 + sg * 16, g);
    }
#pragma unroll
    for (int i = 0; i < 2; i++) {       // B: 8KB (2 planes x 64 x 64)
        int e = tid + i * 256;
        int pl = e >> 8, r = (e >> 2) & 63, sg = e & 3;
        const char* g = (const char*)((pl ? zl : zh) + (size_t)r * zstride + colbase) + sg * 16;
        CP16(sb + 2 * WPL_ + pl * ZPL_ + r * 80 + sg * 16, g);
    }
}

__device__ void gemm_cell(uint32_t smb,
        const int8_t* __restrict__ Wqh, const int8_t* __restrict__ Wql,
        int nchunks, int ntiles, int ksplit,
        const int8_t* __restrict__ xh, const int8_t* __restrict__ xl, int xstride, int xchunks,
        const int8_t* __restrict__ zh, const int8_t* __restrict__ zl, int zstride,
        float* __restrict__ P, int NC, const float* __restrict__ swi) {
    int tl = blockIdx.x;
    if (tl >= ksplit * ntiles) return;
    int ks = tl / ntiles, nt = tl - ks * ntiles;
    int cb = nchunks * ks / ksplit, ce = nchunks * (ks + 1) / ksplit;
    int wid = threadIdx.x >> 5, lane = threadIdx.x & 31;
    int m0 = (wid & 3) * 32, n0 = (wid >> 2) * 32;

    int ahh[2][4][4], amid[2][4][4];
#pragma unroll
    for (int mi = 0; mi < 2; mi++)
#pragma unroll
        for (int ni = 0; ni < 4; ni++)
#pragma unroll
            for (int j = 0; j < 4; j++) { ahh[mi][ni][j] = 0; amid[mi][ni][j] = 0; }

    {
        bool ux = cb < xchunks;
        stage_q(smb, Wqh, Wql, (size_t)(nt * nchunks + cb) * 8192,
                ux ? xh : zh, ux ? xl : zl, ux ? xstride : zstride,
                ux ? cb * 64 : (cb - xchunks) * 64);
        CPCOMMIT();
    }
    for (int c = cb; c < ce; c++) {
        uint32_t b = (uint32_t)(c - cb) & 1u;
        if (c + 1 < ce) {
            int cn = c + 1;
            bool ux = cn < xchunks;
            stage_q(smb + (b ^ 1u) * QBUF_, Wqh, Wql, (size_t)(nt * nchunks + cn) * 8192,
                    ux ? xh : zh, ux ? xl : zl, ux ? xstride : zstride,
                    ux ? cn * 64 : (cn - xchunks) * 64);
            CPCOMMIT();
            CPWAIT1();
        } else {
            CPWAIT0();
        }
        __syncthreads();
        uint32_t base = smb + b * QBUF_;
#pragma unroll
        for (int s = 0; s < 2; s++) {
            unsigned Ah[2][4], Al[2][4], Bh[2][4], Bl[2][4];
#pragma unroll
            for (int mt = 0; mt < 2; mt++) {
                uint32_t ra = base + (uint32_t)(m0 + mt * 16 + ((lane >> 3) & 1) * 8 + (lane & 7)) * 80
                            + s * 32 + (lane >> 4) * 16;
                LDX4(Ah[mt], ra);
                LDX4(Al[mt], ra + WPL_);
            }
#pragma unroll
            for (int nf = 0; nf < 2; nf++) {
                uint32_t rb = base + 2 * WPL_
                            + (uint32_t)(n0 + nf * 16 + (lane >> 4) * 8 + (lane & 7)) * 80
                            + s * 32 + ((lane >> 3) & 1) * 16;
                LDX4(Bh[nf], rb);
                LDX4(Bl[nf], rb + ZPL_);
            }
#pragma unroll
            for (int mi = 0; mi < 2; mi++)
#pragma unroll
                for (int ni = 0; ni < 4; ni++) {
                    unsigned b0h = Bh[ni >> 1][(ni & 1) * 2], b1h = Bh[ni >> 1][(ni & 1) * 2 + 1];
                    unsigned b0l = Bl[ni >> 1][(ni & 1) * 2], b1l = Bl[ni >> 1][(ni & 1) * 2 + 1];
                    imma(ahh[mi][ni],  Ah[mi], b0h, b1h);
                    imma(amid[mi][ni], Ah[mi], b0l, b1l);
                    imma(amid[mi][ni], Al[mi], b0h, b1h);
                }
        }
        __syncthreads();
    }
    // epilogue: dequant + store P[(ks*64+batch)*NC + neuron]
    int g = lane >> 2, t4 = lane & 3;
    float sw4[2][2];
#pragma unroll
    for (int mi = 0; mi < 2; mi++)
#pragma unroll
        for (int jj = 0; jj < 2; jj++)
            sw4[mi][jj] = swi[nt * 128 + m0 + mi * 16 + g + jj * 8];
#pragma unroll
    for (int mi = 0; mi < 2; mi++)
#pragma unroll
        for (int ni = 0; ni < 4; ni++)
#pragma unroll
            for (int j = 0; j < 4; j++) {
                int row = m0 + mi * 16 + g + (j >> 1) * 8;
                int col = n0 + ni * 8 + t4 * 2 + (j & 1);
                float v = fmaf((float)ahh[mi][ni][j], 65536.f, (float)amid[mi][ni][j] * 256.f)
                          * sw4[mi][j >> 1];
                P[(size_t)(ks * 64 + col) * NC + nt * 128 + row] = v;
            }
}

// ================= fused reduce + bias + CfC pointwise =================
__device__ void pointwise(const float* __restrict__ P, int ksplit, int NC, int Nhp, int Nh,
                          const float* __restrict__ bg, const float* __restrict__ bh,
                          const float* __restrict__ bfg, const float* __restrict__ bfh,
                          float ts, float* __restrict__ Hf,
                          int8_t* __restrict__ d0h, int8_t* __restrict__ d0l, int d0s, int d0off,
                          int8_t* __restrict__ d1h, int8_t* __restrict__ d1l, int d1s, int d1off,
                          float* __restrict__ y, int t) {
    int tot = B_ * Nh;
    for (int idx = blockIdx.x * blockDim.x + threadIdx.x; idx < tot; idx += gridDim.x * blockDim.x) {
        int m = idx / Nh, n = idx - m * Nh;
        float s0 = 0.f, s1 = 0.f, s2 = 0.f, s3 = 0.f;
        for (int ks = 0; ks < ksplit; ks++) {
            const float* pb = P + (size_t)(ks * 64 + m) * NC + n;
            s0 += __ldcg(pb);
            s1 += __ldcg(pb + Nhp);
            s2 += __ldcg(pb + 2 * Nhp);
            s3 += __ldcg(pb + 3 * Nhp);
        }
        s0 += __ldg(&bg[n]); s1 += __ldg(&bh[n]); s2 += __ldg(&bfg[n]); s3 += __ldg(&bfh[n]);
        float gv = tanhf(s0), hv = tanhf(s1);
        float gate = 1.f / (1.f + expf(-(s2 + ts * s3)));
        float ov = gv * (1.f - gate) + hv * gate;
        Hf[idx] = ov;
        int8_t hi, lo;
        q_split(ov, QSCL_, hi, lo);
        d0h[(size_t)m * d0s + d0off + n] = hi;
        d0l[(size_t)m * d0s + d0off + n] = lo;
        if (d1h) {
            d1h[(size_t)m * d1s + d1off + n] = hi;
            d1l[(size_t)m * d1s + d1off + n] = lo;
        }
        if (y) y[((size_t)m * S_ + t) * N3_ + n] = ov;
    }
}

// ================= persistent time-loop kernel =================
__global__ __launch_bounds__(NTHR_, 1)
void k_main(const float* __restrict__ tspans, float* __restrict__ out,
            const float* __restrict__ bg1, const float* __restrict__ bh1,
            const float* __restrict__ bfg1, const float* __restrict__ bfh1,
            const float* __restrict__ bg2, const float* __restrict__ bh2,
            const float* __restrict__ bfg2, const float* __restrict__ bfh2,
            const float* __restrict__ bg3, const float* __restrict__ bh3,
            const float* __restrict__ bfg3, const float* __restrict__ bfh3) {
    extern __shared__ char smraw[];
    uint32_t raw32;
    asm("{ .reg .u64 t; cvta.to.shared.u64 t, %1; cvt.u32.u64 %0, t; }" : "=r"(raw32) : "l"(smraw));
    uint32_t smb = (raw32 + 127u) & ~127u;

    for (int t = 0; t < S_; t++) {
        float ts = __ldg(&tspans[t]);

        gemm_cell(smb, g_W1qh, g_W1ql, C1_, T1_, KS1_,
                  g_Xqh + (size_t)t * B_ * INF_, g_Xql + (size_t)t * B_ * INF_, INF_, 8,
                  g_H1qh, g_H1ql, H1P_, g_P1, NC1_, g_swi1);
        grid_barrier();
        pointwise(g_P1, KS1_, NC1_, NHP1_, N1_, bg1, bh1, bfg1, bfh1, ts, g_H1f,
                  g_H1qh, g_H1ql, H1P_, 0,
                  g_Z2qh, g_Z2ql, Z2P_, 0, nullptr, t);
        grid_barrier();

        gemm_cell(smb, g_W2qh, g_W2ql, C2_, T2_, KS2_,
                  nullptr, nullptr, 0, 0,
                  g_Z2qh, g_Z2ql, Z2P_, g_P2, NC2_, g_swi2);
        grid_barrier();
        pointwise(g_P2, KS2_, NC2_, NHP2_, N2_, bg2, bh2, bfg2, bfh2, ts, g_H2f,
                  g_Z2qh, g_Z2ql, Z2P_, N1_,
                  g_Z3qh, g_Z3ql, Z3P_, 0, nullptr, t);
        grid_barrier();

        gemm_cell(smb, g_W3qh, g_W3ql, C3_, T3_, KS3_,
                  nullptr, nullptr, 0, 0,
                  g_Z3qh, g_Z3ql, Z3P_, g_P3, NC3_, g_swi3);
        grid_barrier();
        pointwise(g_P3, KS3_, NC3_, NHP3_, N3_, bg3, bh3, bfg3, bfh3, ts, g_H3f,
                  g_Z3qh, g_Z3ql, Z3P_, N2_,
                  nullptr, nullptr, 0, 0, out, t);
        grid_barrier();
    }

    float* hf = out + (size_t)B_ * S_ * N3_;
    for (int i = blockIdx.x * blockDim.x + threadIdx.x; i < B_ * NU_; i += gridDim.x * blockDim.x) {
        int m = i / NU_, c = i - m * NU_;
        float v;
        if (c < N1_)            v = __ldcg(&g_H1f[m * N1_ + c]);
        else if (c < N1_ + N2_) v = __ldcg(&g_H2f[m * N2_ + (c - N1_)]);
        else                    v = __ldcg(&g_H3f[m * N3_ + (c - N1_ - N2_)]);
        hf[i] = v;
    }
}

// ================= launch =================
extern "C" void kernel_launch(void* const* d_in, const int* in_sizes, int n_in,
                              void* d_out, int out_size) {
    const float* x    = (const float*)d_in[0];
    const float* h0   = (const float*)d_in[1];
    const float* tsp  = (const float*)d_in[2];
    const float* Wg1  = (const float*)d_in[3];
    const float* Wh1  = (const float*)d_in[4];
    const float* Wfg1 = (const float*)d_in[5];
    const float* Wfh1 = (const float*)d_in[6];
    const float* bg1  = (const float*)d_in[7];
    const float* bh1  = (const float*)d_in[8];
    const float* bfg1 = (const float*)d_in[9];
    const float* bfh1 = (const float*)d_in[10];
    const float* msk1 = (const float*)d_in[11];
    const float* Wg2  = (const float*)d_in[12];
    const float* Wh2  = (const float*)d_in[13];
    const float* Wfg2 = (const float*)d_in[14];
    const float* Wfh2 = (const float*)d_in[15];
    const float* bg2  = (const float*)d_in[16];
    const float* bh2  = (const float*)d_in[17];
    const float* bfg2 = (const float*)d_in[18];
    const float* bfh2 = (const float*)d_in[19];
    const float* msk2 = (const float*)d_in[20];
    const float* Wg3  = (const float*)d_in[21];
    const float* Wh3  = (const float*)d_in[22];
    const float* Wfg3 = (const float*)d_in[23];
    const float* Wfh3 = (const float*)d_in[24];
    const float* bg3  = (const float*)d_in[25];
    const float* bh3  = (const float*)d_in[26];
    const float* bfg3 = (const float*)d_in[27];
    const float* bfh3 = (const float*)d_in[28];
    const float* msk3 = (const float*)d_in[29];
    float* out = (float*)d_out;

    cudaFuncSetAttribute(k_main, cudaFuncAttributeMaxDynamicSharedMemorySize, SMEMQ_);

    k_prepA<<<PA_W_ + PA_X_ + PA_H_, NTHR_>>>(x, h0,
        Wg1, Wh1, Wfg1, Wfh1, msk1, Wg2, Wh2, Wfg2, Wfh2, msk2, Wg3, Wh3, Wfg3, Wfh3, msk3);
    k_prepB<<<T1_ * C1_ + T2_ * C2_ + T3_ * C3_, NTHR_>>>(
        Wg1, Wh1, Wfg1, Wfh1, msk1, Wg2, Wh2, Wfg2, Wfh2, msk2, Wg3, Wh3, Wfg3, Wfh3, msk3);
    k_main<<<NBLK_, NTHR_, SMEMQ_>>>(tsp, out,
                                     bg1, bh1, bfg1, bfh1,
                                     bg2, bh2, bfg2, bfh2,
                                     bg3, bh3, bfg3, bfh3);
    (void)in_sizes; (void)n_in; (void)out_size;
}

// round 12
// speedup vs baseline: 2.0574x; 2.0574x over previous
#include <cuda_runtime.h>
#include <cuda_bf16.h>
#include <mma.h>
#include <cmath>
#include <cstdint>

using namespace nvcuda;

// ---------------- problem constants ----------------
#define B_    64
#define S_    32
#define INF_  512
#define N1_   1229
#define N2_   819
#define N3_   512
#define NU_   2560
#define K1_   1741
#define K2_   2048
#define K3_   1331
#define NHP1_ 1248
#define NHP2_ 832
#define NHP3_ 512
#define NC1_  4992
#define NC2_  3328
#define NC3_  2048
#define T1_   39
#define T2_   26
#define T3_   16
#define C1_   28
#define C2_   32
#define C3_   21
#define Z1P_  1792
#define Z2P_  2048
#define Z3P_  1344
#define KS1_  3               // item counts: 117 / 130 / 144
#define KS2_  5
#define KS3_  9
#define NBLK_ 148
#define NTHR_ 256

#define I1_   (KS1_ * T1_)    // 117
#define I2_   (KS2_ * T2_)    // 130
#define I3_   (KS3_ * T3_)    // 144

// smem buffer layout (per buffer): Ahi[128x72] Alo Bhi[64x72] Blo
#define A_PL_   18432
#define B_PL_   9216
#define BUFSZ_  55296
#define SMEM_RAW_ (2 * BUFSZ_ + 256)

// ---------------- device scratch ----------------
__device__ __nv_bfloat16 g_W1hi[(size_t)T1_ * C1_ * 8192];
__device__ __nv_bfloat16 g_W1lo[(size_t)T1_ * C1_ * 8192];
__device__ __nv_bfloat16 g_W2hi[(size_t)T2_ * C2_ * 8192];
__device__ __nv_bfloat16 g_W2lo[(size_t)T2_ * C2_ * 8192];
__device__ __nv_bfloat16 g_W3hi[(size_t)T3_ * C3_ * 8192];
__device__ __nv_bfloat16 g_W3lo[(size_t)T3_ * C3_ * 8192];
__device__ __nv_bfloat16 g_Xhi[(size_t)S_ * B_ * INF_];
__device__ __nv_bfloat16 g_Xlo[(size_t)S_ * B_ * INF_];
__device__ __nv_bfloat16 g_Z1h[B_ * Z1P_], g_Z1l[B_ * Z1P_];
__device__ __nv_bfloat16 g_Z2h[B_ * Z2P_], g_Z2l[B_ * Z2P_];
__device__ __nv_bfloat16 g_Z3h[B_ * Z3P_], g_Z3l[B_ * Z3P_];
__device__ float g_P1[(size_t)KS1_ * B_ * NC1_];
__device__ float g_P2[(size_t)KS2_ * B_ * NC2_];
__device__ float g_P3[(size_t)KS3_ * B_ * NC3_];
__device__ float g_H1f[B_ * N1_], g_H2f[B_ * N2_], g_H3f[B_ * N3_];
__device__ unsigned g_bar_cnt;
__device__ volatile unsigned g_bar_epoch;

// ---------------- async copy helpers ----------------
#define CP16(dst, src)  asm volatile("cp.async.ca.shared.global [%0], [%1], 16;" :: "r"(dst), "l"(src))
#define CPCOMMIT()      asm volatile("cp.async.commit_group;")
#define CPWAIT0()       asm volatile("cp.async.wait_group 0;")
#define CPWAIT1()       asm volatile("cp.async.wait_group 1;")

// ---------------- grid-wide barrier (tid0-only fences; cumulative-fence correct) ----------------
__device__ __forceinline__ void grid_barrier() {
    __syncthreads();
    if (threadIdx.x == 0) {
        __threadfence();
        unsigned e = g_bar_epoch;
        if (atomicAdd(&g_bar_cnt, 1u) == gridDim.x - 1u) {
            g_bar_cnt = 0u;
            __threadfence();
            g_bar_epoch = e + 1u;
        } else {
            while (g_bar_epoch == e) { }
        }
        __threadfence();
    }
    __syncthreads();
}

// ---------------- weight prep: mask, split bf16 hi/lo, flat [tile][chunk][128][64] ----------------
__global__ void k_prep(const float* __restrict__ Wg, const float* __restrict__ Wh,
                       const float* __restrict__ Wfg, const float* __restrict__ Wfh,
                       const float* __restrict__ Msk,
                       __nv_bfloat16* __restrict__ Dhi, __nv_bfloat16* __restrict__ Dlo,
                       int Nh, int K, int Nhp, int nchunks) {
    int blk = blockIdx.x;
    int tile = blk / nchunks, chunk = blk - tile * nchunks;
    size_t base = (size_t)blk * 8192;
    for (int e = threadIdx.x; e < 8192; e += blockDim.x) {
        int row = e >> 6, col = e & 63;
        int nc = tile * 128 + row;
        int hd = nc / Nhp, n = nc - hd * Nhp;
        int kk = chunk * 64 + col;
        float v = 0.f;
        if (n < Nh && kk < K) {
            const float* W = (hd == 0) ? Wg : (hd == 1) ? Wh : (hd == 2) ? Wfg : Wfh;
            v = W[(size_t)n * K + kk] * Msk[(size_t)n * K + kk];
        }
        __nv_bfloat16 hi = __float2bfloat16(v);
        __nv_bfloat16 lo = __float2bfloat16(v - __bfloat162float(hi));
        Dhi[base + e] = hi;
        Dlo[base + e] = lo;
    }
}

// ---------------- x split to bf16 hi/lo planes, [t][batch][512] ----------------
__global__ void k_xprep(const float* __restrict__ x) {
    int i = blockIdx.x * blockDim.x + threadIdx.x;
    if (i < S_ * B_ * INF_) {
        int f = i & (INF_ - 1);
        int r = i >> 9;
        int t = r / B_, b = r - t * B_;
        float v = x[((size_t)b * S_ + t) * INF_ + f];
        __nv_bfloat16 hi = __float2bfloat16(v);
        g_Xhi[i] = hi;
        g_Xlo[i] = __float2bfloat16(v - __bfloat162float(hi));
    }
}

// ---------------- init: scatter h0 into fp32 + bf16 planes, zero pad cols ----------------
__global__ void k_init(const float* __restrict__ h0) {
    int stride = gridDim.x * blockDim.x;
    for (int i = blockIdx.x * blockDim.x + threadIdx.x; i < B_ * NU_; i += stride) {
        int m = i / NU_, c = i - m * NU_;
        float v = h0[i];
        __nv_bfloat16 hi = __float2bfloat16(v);
        __nv_bfloat16 lo = __float2bfloat16(v - __bfloat162float(hi));
        if (c < N1_) {
            g_H1f[m * N1_ + c] = v;
            g_Z1h[m * Z1P_ + INF_ + c] = hi;  g_Z1l[m * Z1P_ + INF_ + c] = lo;
        } else if (c < N1_ + N2_) {
            int cc = c - N1_;
            g_H2f[m * N2_ + cc] = v;
            g_Z2h[m * Z2P_ + N1_ + cc] = hi;  g_Z2l[m * Z2P_ + N1_ + cc] = lo;
        } else {
            int cc = c - N1_ - N2_;
            g_H3f[m * N3_ + cc] = v;
            g_Z3h[m * Z3P_ + N2_ + cc] = hi;  g_Z3l[m * Z3P_ + N2_ + cc] = lo;
        }
    }
    for (int i = blockIdx.x * blockDim.x + threadIdx.x; i < B_ * (Z1P_ - K1_); i += stride) {
        int m = i / (Z1P_ - K1_), c = K1_ + (i - m * (Z1P_ - K1_));
        g_Z1h[m * Z1P_ + c] = __float2bfloat16(0.f);
        g_Z1l[m * Z1P_ + c] = __float2bfloat16(0.f);
    }
    for (int i = blockIdx.x * blockDim.x + threadIdx.x; i < B_ * (Z3P_ - K3_); i += stride) {
        int m = i / (Z3P_ - K3_), c = K3_ + (i - m * (Z3P_ - K3_));
        g_Z3h[m * Z3P_ + c] = __float2bfloat16(0.f);
        g_Z3l[m * Z3P_ + c] = __float2bfloat16(0.f);
    }
}

// ---------------- chunk staging into smem via cp.async ----------------
__device__ __forceinline__ void stage_chunk(uint32_t sb,
        const __nv_bfloat16* __restrict__ Whi, const __nv_bfloat16* __restrict__ Wlo,
        size_t wbase,
        const __nv_bfloat16* __restrict__ zh, const __nv_bfloat16* __restrict__ zl,
        int zstride, int colbase) {
    int tid = threadIdx.x;
#pragma unroll
    for (int i = 0; i < 8; i++) {                 // A: 32KB
        int e = tid + i * 256;
        int plane = e >> 10, r = (e >> 3) & 127, u = e & 7;
        const char* g = (const char*)((plane ? Wlo : Whi) + wbase) + r * 128 + u * 16;
        CP16(sb + plane * A_PL_ + r * 144 + u * 16, g);
    }
#pragma unroll
    for (int i = 0; i < 4; i++) {                 // B: 16KB
        int e = tid + i * 256;
        int plane = e >> 9, r = (e >> 3) & 63, u = e & 7;
        const char* g = (const char*)((plane ? zl : zh) + (size_t)r * zstride + colbase) + u * 16;
        CP16(sb + 2 * A_PL_ + plane * B_PL_ + r * 144 + u * 16, g);
    }
}

// ---------------- one GEMM tile (wmma bf16, split-hi/lo, reg accum) ----------------
typedef wmma::fragment<wmma::matrix_a, 16, 16, 16, __nv_bfloat16, wmma::row_major> FragA;
typedef wmma::fragment<wmma::matrix_b, 16, 16, 16, __nv_bfloat16, wmma::col_major> FragB;
typedef wmma::fragment<wmma::accumulator, 16, 16, 16, float> FragC;

__device__ void gemm_tile(char* smc, uint32_t smb,
        const __nv_bfloat16* __restrict__ Whi, const __nv_bfloat16* __restrict__ Wlo,
        int nchunks, int ksplit, int ks, int nt,
        const __nv_bfloat16* __restrict__ xh, const __nv_bfloat16* __restrict__ xl,
        int xstride, int xchunks,
        const __nv_bfloat16* __restrict__ zh, const __nv_bfloat16* __restrict__ zl,
        int zstride,
        float* __restrict__ P, int NC) {
    int cb = nchunks * ks / ksplit, ce = nchunks * (ks + 1) / ksplit;
    int wid = threadIdx.x >> 5;
    int m0 = (wid & 3) * 32, n0 = (wid >> 2) * 32;

    FragC acc[2][2];
#pragma unroll
    for (int mi = 0; mi < 2; mi++)
#pragma unroll
        for (int ni = 0; ni < 2; ni++) wmma::fill_fragment(acc[mi][ni], 0.f);

    {
        bool ux = cb < xchunks;
        stage_chunk(smb, Whi, Wlo, (size_t)(nt * nchunks + cb) * 8192,
                    ux ? xh : zh, ux ? xl : zl, ux ? xstride : zstride, cb * 64);
        CPCOMMIT();
    }
    for (int c = cb; c < ce; c++) {
        uint32_t b = (uint32_t)(c - cb) & 1u;
        if (c + 1 < ce) {
            int cn = c + 1;
            bool ux = cn < xchunks;
            stage_chunk(smb + (b ^ 1u) * BUFSZ_, Whi, Wlo, (size_t)(nt * nchunks + cn) * 8192,
                        ux ? xh : zh, ux ? xl : zl, ux ? xstride : zstride, cn * 64);
            CPCOMMIT();
            CPWAIT1();
        } else {
            CPWAIT0();
        }
        __syncthreads();
        const __nv_bfloat16* A_h = (const __nv_bfloat16*)(smc + b * BUFSZ_);
        const __nv_bfloat16* A_l = (const __nv_bfloat16*)(smc + b * BUFSZ_ + A_PL_);
        const __nv_bfloat16* B_h = (const __nv_bfloat16*)(smc + b * BUFSZ_ + 2 * A_PL_);
        const __nv_bfloat16* B_l = (const __nv_bfloat16*)(smc + b * BUFSZ_ + 2 * A_PL_ + B_PL_);
#pragma unroll
        for (int k = 0; k < 4; k++) {
            FragA ah[2], al[2];
            FragB bh[2], bl[2];
            wmma::load_matrix_sync(ah[0], A_h + (m0 +  0) * 72 + k * 16, 72);
            wmma::load_matrix_sync(ah[1], A_h + (m0 + 16) * 72 + k * 16, 72);
            wmma::load_matrix_sync(al[0], A_l + (m0 +  0) * 72 + k * 16, 72);
            wmma::load_matrix_sync(al[1], A_l + (m0 + 16) * 72 + k * 16, 72);
            wmma::load_matrix_sync(bh[0], B_h + (n0 +  0) * 72 + k * 16, 72);
            wmma::load_matrix_sync(bh[1], B_h + (n0 + 16) * 72 + k * 16, 72);
            wmma::load_matrix_sync(bl[0], B_l + (n0 +  0) * 72 + k * 16, 72);
            wmma::load_matrix_sync(bl[1], B_l + (n0 + 16) * 72 + k * 16, 72);
#pragma unroll
            for (int mi = 0; mi < 2; mi++)
#pragma unroll
                for (int ni = 0; ni < 2; ni++) {
                    wmma::mma_sync(acc[mi][ni], ah[mi], bh[ni], acc[mi][ni]);
                    wmma::mma_sync(acc[mi][ni], ah[mi], bl[ni], acc[mi][ni]);
                    wmma::mma_sync(acc[mi][ni], al[mi], bh[ni], acc[mi][ni]);
                }
        }
        __syncthreads();
    }
#pragma unroll
    for (int mi = 0; mi < 2; mi++)
#pragma unroll
        for (int ni = 0; ni < 2; ni++) {
            float* pp = P + (size_t)(ks * 64 + n0 + ni * 16) * NC + nt * 128 + m0 + mi * 16;
            wmma::store_matrix_sync(pp, acc[mi][ni], NC, wmma::mem_col_major);
        }
}

// ---------------- fused reduce + bias + CfC pointwise ----------------
__device__ void pointwise(const float* __restrict__ P, int ksplit, int NC, int Nhp, int Nh,
                          const float* __restrict__ bg, const float* __restrict__ bh,
                          const float* __restrict__ bfg, const float* __restrict__ bfh,
                          float ts, float* __restrict__ Hf,
                          __nv_bfloat16* __restrict__ d0h, __nv_bfloat16* __restrict__ d0l,
                          int d0s, int d0off,
                          __nv_bfloat16* __restrict__ d1h, __nv_bfloat16* __restrict__ d1l,
                          int d1s, int d1off,
                          float* __restrict__ y, int t) {
    int tot = B_ * Nh;
    for (int idx = blockIdx.x * blockDim.x + threadIdx.x; idx < tot; idx += gridDim.x * blockDim.x) {
        int m = idx / Nh, n = idx - m * Nh;
        float s0 = 0.f, s1 = 0.f, s2 = 0.f, s3 = 0.f;
        for (int ks = 0; ks < ksplit; ks++) {
            const float* pb = P + (size_t)(ks * 64 + m) * NC + n;
            s0 += __ldcg(pb);
            s1 += __ldcg(pb + Nhp);
            s2 += __ldcg(pb + 2 * Nhp);
            s3 += __ldcg(pb + 3 * Nhp);
        }
        s0 += __ldg(&bg[n]); s1 += __ldg(&bh[n]); s2 += __ldg(&bfg[n]); s3 += __ldg(&bfh[n]);
        float gv = tanhf(s0), hv = tanhf(s1);
        float gate = 1.f / (1.f + __expf(-(s2 + ts * s3)));
        float ov = gv * (1.f - gate) + hv * gate;
        Hf[idx] = ov;
        __nv_bfloat16 hi = __float2bfloat16(ov);
        __nv_bfloat16 lo = __float2bfloat16(ov - __bfloat162float(hi));
        d0h[(size_t)m * d0s + d0off + n] = hi;
        d0l[(size_t)m * d0s + d0off + n] = lo;
        if (d1h) {
            d1h[(size_t)m * d1s + d1off + n] = hi;
            d1l[(size_t)m * d1s + d1off + n] = lo;
        }
        if (y) y[((size_t)m * S_ + t) * N3_ + n] = ov;
    }
}

// ---------------- persistent time-loop kernel (software-pipelined cells) ----------------
__global__ __launch_bounds__(NTHR_, 1)
void k_main(const float* __restrict__ tspans, float* __restrict__ out,
            const float* __restrict__ bg1, const float* __restrict__ bh1,
            const float* __restrict__ bfg1, const float* __restrict__ bfh1,
            const float* __restrict__ bg2, const float* __restrict__ bh2,
            const float* __restrict__ bfg2, const float* __restrict__ bfh2,
            const float* __restrict__ bg3, const float* __restrict__ bh3,
            const float* __restrict__ bfg3, const float* __restrict__ bfh3) {
    extern __shared__ char smraw[];
    uint32_t raw32;
    asm("{ .reg .u64 t; cvta.to.shared.u64 t, %1; cvt.u32.u64 %0, t; }" : "=r"(raw32) : "l"(smraw));
    uint32_t smb = (raw32 + 127u) & ~127u;
    char* smc = smraw + (smb - raw32);
    int bid = blockIdx.x;

    // tile runners
    auto g1 = [&](int tile, int t) {
        int ks = tile / T1_, nt = tile - ks * T1_;
        gemm_tile(smc, smb, g_W1hi, g_W1lo, C1_, KS1_, ks, nt,
                  g_Xhi + (size_t)t * B_ * INF_, g_Xlo + (size_t)t * B_ * INF_, INF_, 8,
                  g_Z1h, g_Z1l, Z1P_, g_P1, NC1_);
    };
    auto g2 = [&](int tile) {
        int ks = tile / T2_, nt = tile - ks * T2_;
        gemm_tile(smc, smb, g_W2hi, g_W2lo, C2_, KS2_, ks, nt,
                  (const __nv_bfloat16*)nullptr, (const __nv_bfloat16*)nullptr, 0, 0,
                  g_Z2h, g_Z2l, Z2P_, g_P2, NC2_);
    };
    auto g3 = [&](int tile) {
        int ks = tile / T3_, nt = tile - ks * T3_;
        gemm_tile(smc, smb, g_W3hi, g_W3lo, C3_, KS3_, ks, nt,
                  (const __nv_bfloat16*)nullptr, (const __nv_bfloat16*)nullptr, 0, 0,
                  g_Z3h, g_Z3l, Z3P_, g_P3, NC3_);
    };

    // prime: GEMM1(0)
    for (int tl = bid; tl < I1_; tl += NBLK_) g1(tl, 0);
    grid_barrier();

    // pipelined loop: P-phase: PW1(t) | PW2(t-1) | PW3(t-2); G-phase: G2(t) | G1(t+1) | G3(t-1)
    for (int t = 0; t <= S_ + 1; t++) {
        float ts0 = (t < S_)                ? __ldg(&tspans[t])     : 0.f;
        float ts1 = (t >= 1 && t - 1 < S_)  ? __ldg(&tspans[t - 1]) : 0.f;
        float ts2 = (t >= 2)                ? __ldg(&tspans[t - 2]) : 0.f;

        // ---- P-phase ----
        if (t < S_)
            pointwise(g_P1, KS1_, NC1_, NHP1_, N1_, bg1, bh1, bfg1, bfh1, ts0, g_H1f,
                      g_Z1h, g_Z1l, Z1P_, INF_,
                      g_Z2h, g_Z2l, Z2P_, 0, nullptr, t);
        if (t >= 1 && t - 1 < S_)
            pointwise(g_P2, KS2_, NC2_, NHP2_, N2_, bg2, bh2, bfg2, bfh2, ts1, g_H2f,
                      g_Z2h, g_Z2l, Z2P_, N1_,
                      g_Z3h, g_Z3l, Z3P_, 0, nullptr, t - 1);
        if (t >= 2)
            pointwise(g_P3, KS3_, NC3_, NHP3_, N3_, bg3, bh3, bfg3, bfh3, ts2, g_H3f,
                      g_Z3h, g_Z3l, Z3P_, N2_,
                      nullptr, nullptr, 0, 0, out, t - 2);
        grid_barrier();

        // ---- G-phase ----
        bool h2 = (t < S_);            // GEMM2(t)
        bool h1 = (t + 1 < S_);        // GEMM1(t+1)
        bool h3 = (t >= 1 && t - 1 < S_); // GEMM3(t-1)
        if (h1 && h2 && h3) {
            // balanced static map: 117 c1 + 130 c2 + 144 c3 over 148 CTAs (~15.7 units each)
            if (bid < I1_) {
                g1(bid, t + 1);
                if (bid < 104) g2(bid);
                else { int u = (bid - 104) * 2; g3(u); g3(u + 1); }
            } else if (bid < 143) {
                g2(104 + (bid - 117));
                int u = 26 + (bid - 117) * 4;
                g3(u); g3(u + 1); g3(u + 2); g3(u + 3);
            } else {
                int u = 130 + (bid - 143) * 3;
                g3(u);
                if (u + 1 < I3_) g3(u + 1);
                if (u + 2 < I3_) g3(u + 2);
            }
        } else {
            int n2 = h2 ? I2_ : 0, n1 = h1 ? I1_ : 0, n3 = h3 ? I3_ : 0;
            int tot = n2 + n1 + n3;
            for (int tl = bid; tl < tot; tl += NBLK_) {
                if (tl < n2) g2(tl);
                else if (tl < n2 + n1) g1(tl - n2, t + 1);
                else g3(tl - n2 - n1);
            }
        }
        grid_barrier();
    }

    // h_final = concat(h1,h2,h3) fp32
    float* hf = out + (size_t)B_ * S_ * N3_;
    for (int i = bid * blockDim.x + threadIdx.x; i < B_ * NU_; i += gridDim.x * blockDim.x) {
        int m = i / NU_, c = i - m * NU_;
        float v;
        if (c < N1_)            v = __ldcg(&g_H1f[m * N1_ + c]);
        else if (c < N1_ + N2_) v = __ldcg(&g_H2f[m * N2_ + (c - N1_)]);
        else                    v = __ldcg(&g_H3f[m * N3_ + (c - N1_ - N2_)]);
        hf[i] = v;
    }
}

// ---------------- launch ----------------
extern "C" void kernel_launch(void* const* d_in, const int* in_sizes, int n_in,
                              void* d_out, int out_size) {
    const float* x    = (const float*)d_in[0];
    const float* h0   = (const float*)d_in[1];
    const float* tsp  = (const float*)d_in[2];
    const float* Wg1  = (const float*)d_in[3];
    const float* Wh1  = (const float*)d_in[4];
    const float* Wfg1 = (const float*)d_in[5];
    const float* Wfh1 = (const float*)d_in[6];
    const float* bg1  = (const float*)d_in[7];
    const float* bh1  = (const float*)d_in[8];
    const float* bfg1 = (const float*)d_in[9];
    const float* bfh1 = (const float*)d_in[10];
    const float* msk1 = (const float*)d_in[11];
    const float* Wg2  = (const float*)d_in[12];
    const float* Wh2  = (const float*)d_in[13];
    const float* Wfg2 = (const float*)d_in[14];
    const float* Wfh2 = (const float*)d_in[15];
    const float* bg2  = (const float*)d_in[16];
    const float* bh2  = (const float*)d_in[17];
    const float* bfg2 = (const float*)d_in[18];
    const float* bfh2 = (const float*)d_in[19];
    const float* msk2 = (const float*)d_in[20];
    const float* Wg3  = (const float*)d_in[21];
    const float* Wh3  = (const float*)d_in[22];
    const float* Wfg3 = (const float*)d_in[23];
    const float* Wfh3 = (const float*)d_in[24];
    const float* bg3  = (const float*)d_in[25];
    const float* bh3  = (const float*)d_in[26];
    const float* bfg3 = (const float*)d_in[27];
    const float* bfh3 = (const float*)d_in[28];
    const float* msk3 = (const float*)d_in[29];
    float* out = (float*)d_out;

    cudaFuncSetAttribute(k_main, cudaFuncAttributeMaxDynamicSharedMemorySize, SMEM_RAW_);

    __nv_bfloat16 *w1hi, *w1lo, *w2hi, *w2lo, *w3hi, *w3lo;
    cudaGetSymbolAddress((void**)&w1hi, g_W1hi);
    cudaGetSymbolAddress((void**)&w1lo, g_W1lo);
    cudaGetSymbolAddress((void**)&w2hi, g_W2hi);
    cudaGetSymbolAddress((void**)&w2lo, g_W2lo);
    cudaGetSymbolAddress((void**)&w3hi, g_W3hi);
    cudaGetSymbolAddress((void**)&w3lo, g_W3lo);

    k_prep<<<T1_ * C1_, NTHR_>>>(Wg1, Wh1, Wfg1, Wfh1, msk1, w1hi, w1lo, N1_, K1_, NHP1_, C1_);
    k_prep<<<T2_ * C2_, NTHR_>>>(Wg2, Wh2, Wfg2, Wfh2, msk2, w2hi, w2lo, N2_, K2_, NHP2_, C2_);
    k_prep<<<T3_ * C3_, NTHR_>>>(Wg3, Wh3, Wfg3, Wfh3, msk3, w3hi, w3lo, N3_, K3_, NHP3_, C3_);
    k_xprep<<<(S_ * B_ * INF_ + NTHR_ - 1) / NTHR_, NTHR_>>>(x);
    k_init<<<256, NTHR_>>>(h0);
    k_main<<<NBLK_, NTHR_, SMEM_RAW_>>>(tsp, out,
                                        bg1, bh1, bfg1, bfh1,
                                        bg2, bh2, bfg2, bfh2,
                                        bg3, bh3, bfg3, bfh3);
    (void)in_sizes; (void)n_in; (void)out_size;
}

// round 14
// speedup vs baseline: 2.9524x; 1.4350x over previous
#include <cuda_runtime.h>
#include <cuda_fp16.h>
#include <mma.h>
#include <cmath>
#include <cstdint>

using namespace nvcuda;

// ---------------- problem constants ----------------
#define B_    64
#define S_    32
#define INF_  512
#define N1_   1229
#define N2_   819
#define N3_   512
#define NU_   2560
#define K1_   1741
#define K2_   2048
#define K3_   1331
#define NHP1_ 1248
#define NHP2_ 832
#define NHP3_ 512
#define NC1_  4992
#define NC2_  3328
#define NC3_  2048
#define T1_   39
#define T2_   26
#define T3_   16
#define C1_   28
#define C2_   32
#define C3_   21
#define Z1P_  1792
#define Z2P_  2048
#define Z3P_  1344
#define KS1_  3               // item counts: 117 / 130 / 144
#define KS2_  5
#define KS3_  9
#define NBLK_ 148
#define NTHR_ 256

#define I1_   (KS1_ * T1_)    // 117
#define I2_   (KS2_ * T2_)    // 130
#define I3_   (KS3_ * T3_)    // 144

// smem buffer layout (per buffer): A[128x72 fp16] Bhi[64x72] Blo[64x72]
#define A_PL_   18432
#define B_PL_   9216
#define BUFSZ_  36864
#define SMEM_RAW_ (2 * BUFSZ_ + 256)

// ---------------- device scratch ----------------
__device__ __half g_W1[(size_t)T1_ * C1_ * 8192];
__device__ __half g_W2[(size_t)T2_ * C2_ * 8192];
__device__ __half g_W3[(size_t)T3_ * C3_ * 8192];
__device__ __half g_Xhi[(size_t)S_ * B_ * INF_];
__device__ __half g_Xlo[(size_t)S_ * B_ * INF_];
__device__ __half g_Z1h[B_ * Z1P_], g_Z1l[B_ * Z1P_];
__device__ __half g_Z2h[B_ * Z2P_], g_Z2l[B_ * Z2P_];
__device__ __half g_Z3h[B_ * Z3P_], g_Z3l[B_ * Z3P_];
__device__ float g_P1[(size_t)KS1_ * B_ * NC1_];
__device__ float g_P2[(size_t)KS2_ * B_ * NC2_];
__device__ float g_P3[(size_t)KS3_ * B_ * NC3_];
__device__ float g_H1f[B_ * N1_], g_H2f[B_ * N2_], g_H3f[B_ * N3_];
__device__ unsigned g_bar_cnt;
__device__ volatile unsigned g_bar_epoch;

// ---------------- async copy helpers ----------------
#define CP16(dst, src)  asm volatile("cp.async.ca.shared.global [%0], [%1], 16;" :: "r"(dst), "l"(src))
#define CPCOMMIT()      asm volatile("cp.async.commit_group;")
#define CPWAIT0()       asm volatile("cp.async.wait_group 0;")
#define CPWAIT1()       asm volatile("cp.async.wait_group 1;")

// ---------------- grid-wide barrier (tid0-only fences; cumulative-fence correct) ----------------
__device__ __forceinline__ void grid_barrier() {
    __syncthreads();
    if (threadIdx.x == 0) {
        __threadfence();
        unsigned e = g_bar_epoch;
        if (atomicAdd(&g_bar_cnt, 1u) == gridDim.x - 1u) {
            g_bar_cnt = 0u;
            __threadfence();
            g_bar_epoch = e + 1u;
        } else {
            while (g_bar_epoch == e) { }
        }
        __threadfence();
    }
    __syncthreads();
}

// ---------------- weight prep: mask, fp16 (single plane), flat [tile][chunk][128][64] ----------------
__global__ void k_prep(const float* __restrict__ Wg, const float* __restrict__ Wh,
                       const float* __restrict__ Wfg, const float* __restrict__ Wfh,
                       const float* __restrict__ Msk,
                       __half* __restrict__ D,
                       int Nh, int K, int Nhp, int nchunks) {
    int blk = blockIdx.x;
    int tile = blk / nchunks, chunk = blk - tile * nchunks;
    size_t base = (size_t)blk * 8192;
    for (int e = threadIdx.x; e < 8192; e += blockDim.x) {
        int row = e >> 6, col = e & 63;
        int nc = tile * 128 + row;
        int hd = nc / Nhp, n = nc - hd * Nhp;
        int kk = chunk * 64 + col;
        float v = 0.f;
        if (n < Nh && kk < K) {
            const float* W = (hd == 0) ? Wg : (hd == 1) ? Wh : (hd == 2) ? Wfg : Wfh;
            v = W[(size_t)n * K + kk] * Msk[(size_t)n * K + kk];
        }
        D[base + e] = __float2half_rn(v);
    }
}

// ---------------- x split to fp16 hi/lo planes, [t][batch][512] ----------------
__global__ void k_xprep(const float* __restrict__ x) {
    int i = blockIdx.x * blockDim.x + threadIdx.x;
    if (i < S_ * B_ * INF_) {
        int f = i & (INF_ - 1);
        int r = i >> 9;
        int t = r / B_, b = r - t * B_;
        float v = x[((size_t)b * S_ + t) * INF_ + f];
        __half hi = __float2half_rn(v);
        g_Xhi[i] = hi;
        g_Xlo[i] = __float2half_rn(v - __half2float(hi));
    }
}

// ---------------- init: scatter h0 into fp32 + fp16 planes, zero pad cols ----------------
__global__ void k_init(const float* __restrict__ h0) {
    int stride = gridDim.x * blockDim.x;
    for (int i = blockIdx.x * blockDim.x + threadIdx.x; i < B_ * NU_; i += stride) {
        int m = i / NU_, c = i - m * NU_;
        float v = h0[i];
        __half hi = __float2half_rn(v);
        __half lo = __float2half_rn(v - __half2float(hi));
        if (c < N1_) {
            g_H1f[m * N1_ + c] = v;
            g_Z1h[m * Z1P_ + INF_ + c] = hi;  g_Z1l[m * Z1P_ + INF_ + c] = lo;
        } else if (c < N1_ + N2_) {
            int cc = c - N1_;
            g_H2f[m * N2_ + cc] = v;
            g_Z2h[m * Z2P_ + N1_ + cc] = hi;  g_Z2l[m * Z2P_ + N1_ + cc] = lo;
        } else {
            int cc = c - N1_ - N2_;
            g_H3f[m * N3_ + cc] = v;
            g_Z3h[m * Z3P_ + N2_ + cc] = hi;  g_Z3l[m * Z3P_ + N2_ + cc] = lo;
        }
    }
    for (int i = blockIdx.x * blockDim.x + threadIdx.x; i < B_ * (Z1P_ - K1_); i += stride) {
        int m = i / (Z1P_ - K1_), c = K1_ + (i - m * (Z1P_ - K1_));
        g_Z1h[m * Z1P_ + c] = __float2half_rn(0.f);
        g_Z1l[m * Z1P_ + c] = __float2half_rn(0.f);
    }
    for (int i = blockIdx.x * blockDim.x + threadIdx.x; i < B_ * (Z3P_ - K3_); i += stride) {
        int m = i / (Z3P_ - K3_), c = K3_ + (i - m * (Z3P_ - K3_));
        g_Z3h[m * Z3P_ + c] = __float2half_rn(0.f);
        g_Z3l[m * Z3P_ + c] = __float2half_rn(0.f);
    }
}

// ---------------- chunk staging into smem via cp.async ----------------
__device__ __forceinline__ void stage_chunk(uint32_t sb,
        const __half* __restrict__ W, size_t wbase,
        const __half* __restrict__ zh, const __half* __restrict__ zl,
        int zstride, int colbase) {
    int tid = threadIdx.x;
#pragma unroll
    for (int i = 0; i < 4; i++) {                 // A: 16KB (128 rows x 128B)
        int e = tid + i * 256;
        int r = e >> 3, u = e & 7;
        const char* g = (const char*)(W + wbase) + r * 128 + u * 16;
        CP16(sb + r * 144 + u * 16, g);
    }
#pragma unroll
    for (int i = 0; i < 4; i++) {                 // B: 16KB (2 planes x 64 rows x 128B)
        int e = tid + i * 256;
        int plane = e >> 9, r = (e >> 3) & 63, u = e & 7;
        const char* g = (const char*)((plane ? zl : zh) + (size_t)r * zstride + colbase) + u * 16;
        CP16(sb + A_PL_ + plane * B_PL_ + r * 144 + u * 16, g);
    }
}

// ---------------- one GEMM tile (wmma fp16, W 1-plane, Z hi/lo, reg accum) ----------------
typedef wmma::fragment<wmma::matrix_a, 16, 16, 16, __half, wmma::row_major> FragA;
typedef wmma::fragment<wmma::matrix_b, 16, 16, 16, __half, wmma::col_major> FragB;
typedef wmma::fragment<wmma::accumulator, 16, 16, 16, float> FragC;

__device__ void gemm_tile(char* smc, uint32_t smb,
        const __half* __restrict__ W,
        int nchunks, int ksplit, int ks, int nt,
        const __half* __restrict__ xh, const __half* __restrict__ xl,
        int xstride, int xchunks,
        const __half* __restrict__ zh, const __half* __restrict__ zl,
        int zstride,
        float* __restrict__ P, int NC) {
    int cb = nchunks * ks / ksplit, ce = nchunks * (ks + 1) / ksplit;
    int wid = threadIdx.x >> 5;
    int m0 = (wid & 3) * 32, n0 = (wid >> 2) * 32;

    FragC acc[2][2];
#pragma unroll
    for (int mi = 0; mi < 2; mi++)
#pragma unroll
        for (int ni = 0; ni < 2; ni++) wmma::fill_fragment(acc[mi][ni], 0.f);

    {
        bool ux = cb < xchunks;
        stage_chunk(smb, W, (size_t)(nt * nchunks + cb) * 8192,
                    ux ? xh : zh, ux ? xl : zl, ux ? xstride : zstride, cb * 64);
        CPCOMMIT();
    }
    for (int c = cb; c < ce; c++) {
        uint32_t b = (uint32_t)(c - cb) & 1u;
        if (c + 1 < ce) {
            int cn = c + 1;
            bool ux = cn < xchunks;
            stage_chunk(smb + (b ^ 1u) * BUFSZ_, W, (size_t)(nt * nchunks + cn) * 8192,
                        ux ? xh : zh, ux ? xl : zl, ux ? xstride : zstride, cn * 64);
            CPCOMMIT();
            CPWAIT1();
        } else {
            CPWAIT0();
        }
        __syncthreads();
        const __half* A_p = (const __half*)(smc + b * BUFSZ_);
        const __half* B_h = (const __half*)(smc + b * BUFSZ_ + A_PL_);
        const __half* B_l = (const __half*)(smc + b * BUFSZ_ + A_PL_ + B_PL_);
#pragma unroll
        for (int k = 0; k < 4; k++) {
            FragA ah[2];
            FragB bh[2], bl[2];
            wmma::load_matrix_sync(ah[0], A_p + (m0 +  0) * 72 + k * 16, 72);
            wmma::load_matrix_sync(ah[1], A_p + (m0 + 16) * 72 + k * 16, 72);
            wmma::load_matrix_sync(bh[0], B_h + (n0 +  0) * 72 + k * 16, 72);
            wmma::load_matrix_sync(bh[1], B_h + (n0 + 16) * 72 + k * 16, 72);
            wmma::load_matrix_sync(bl[0], B_l + (n0 +  0) * 72 + k * 16, 72);
            wmma::load_matrix_sync(bl[1], B_l + (n0 + 16) * 72 + k * 16, 72);
#pragma unroll
            for (int mi = 0; mi < 2; mi++)
#pragma unroll
                for (int ni = 0; ni < 2; ni++) {
                    wmma::mma_sync(acc[mi][ni], ah[mi], bh[ni], acc[mi][ni]);
                    wmma::mma_sync(acc[mi][ni], ah[mi], bl[ni], acc[mi][ni]);
                }
        }
        __syncthreads();
    }
#pragma unroll
    for (int mi = 0; mi < 2; mi++)
#pragma unroll
        for (int ni = 0; ni < 2; ni++) {
            float* pp = P + (size_t)(ks * 64 + n0 + ni * 16) * NC + nt * 128 + m0 + mi * 16;
            wmma::store_matrix_sync(pp, acc[mi][ni], NC, wmma::mem_col_major);
        }
}

// ---------------- fused reduce + bias + CfC pointwise ----------------
__device__ void pointwise(const float* __restrict__ P, int ksplit, int NC, int Nhp, int Nh,
                          const float* __restrict__ bg, const float* __restrict__ bh,
                          const float* __restrict__ bfg, const float* __restrict__ bfh,
                          float ts, float* __restrict__ Hf,
                          __half* __restrict__ d0h, __half* __restrict__ d0l,
                          int d0s, int d0off,
                          __half* __restrict__ d1h, __half* __restrict__ d1l,
                          int d1s, int d1off,
                          float* __restrict__ y, int t) {
    int tot = B_ * Nh;
    for (int idx = blockIdx.x * blockDim.x + threadIdx.x; idx < tot; idx += gridDim.x * blockDim.x) {
        int m = idx / Nh, n = idx - m * Nh;
        float s0 = 0.f, s1 = 0.f, s2 = 0.f, s3 = 0.f;
        for (int ks = 0; ks < ksplit; ks++) {
            const float* pb = P + (size_t)(ks * 64 + m) * NC + n;
            s0 += __ldcg(pb);
            s1 += __ldcg(pb + Nhp);
            s2 += __ldcg(pb + 2 * Nhp);
            s3 += __ldcg(pb + 3 * Nhp);
        }
        s0 += __ldg(&bg[n]); s1 += __ldg(&bh[n]); s2 += __ldg(&bfg[n]); s3 += __ldg(&bfh[n]);
        float gv = tanhf(s0), hv = tanhf(s1);
        float gate = 1.f / (1.f + __expf(-(s2 + ts * s3)));
        float ov = gv * (1.f - gate) + hv * gate;
        Hf[idx] = ov;
        __half hi = __float2half_rn(ov);
        __half lo = __float2half_rn(ov - __half2float(hi));
        d0h[(size_t)m * d0s + d0off + n] = hi;
        d0l[(size_t)m * d0s + d0off + n] = lo;
        if (d1h) {
            d1h[(size_t)m * d1s + d1off + n] = hi;
            d1l[(size_t)m * d1s + d1off + n] = lo;
        }
        if (y) y[((size_t)m * S_ + t) * N3_ + n] = ov;
    }
}

// ---------------- persistent time-loop kernel (software-pipelined cells) ----------------
__global__ __launch_bounds__(NTHR_, 1)
void k_main(const float* __restrict__ tspans, float* __restrict__ out,
            const float* __restrict__ bg1, const float* __restrict__ bh1,
            const float* __restrict__ bfg1, const float* __restrict__ bfh1,
            const float* __restrict__ bg2, const float* __restrict__ bh2,
            const float* __restrict__ bfg2, const float* __restrict__ bfh2,
            const float* __restrict__ bg3, const float* __restrict__ bh3,
            const float* __restrict__ bfg3, const float* __restrict__ bfh3) {
    extern __shared__ char smraw[];
    uint32_t raw32;
    asm("{ .reg .u64 t; cvta.to.shared.u64 t, %1; cvt.u32.u64 %0, t; }" : "=r"(raw32) : "l"(smraw));
    uint32_t smb = (raw32 + 127u) & ~127u;
    char* smc = smraw + (smb - raw32);
    int bid = blockIdx.x;

    auto g1 = [&](int tile, int t) {
        int ks = tile / T1_, nt = tile - ks * T1_;
        gemm_tile(smc, smb, g_W1, C1_, KS1_, ks, nt,
                  g_Xhi + (size_t)t * B_ * INF_, g_Xlo + (size_t)t * B_ * INF_, INF_, 8,
                  g_Z1h, g_Z1l, Z1P_, g_P1, NC1_);
    };
    auto g2 = [&](int tile) {
        int ks = tile / T2_, nt = tile - ks * T2_;
        gemm_tile(smc, smb, g_W2, C2_, KS2_, ks, nt,
                  (const __half*)nullptr, (const __half*)nullptr, 0, 0,
                  g_Z2h, g_Z2l, Z2P_, g_P2, NC2_);
    };
    auto g3 = [&](int tile) {
        int ks = tile / T3_, nt = tile - ks * T3_;
        gemm_tile(smc, smb, g_W3, C3_, KS3_, ks, nt,
                  (const __half*)nullptr, (const __half*)nullptr, 0, 0,
                  g_Z3h, g_Z3l, Z3P_, g_P3, NC3_);
    };

    // prime: GEMM1(0)
    for (int tl = bid; tl < I1_; tl += NBLK_) g1(tl, 0);
    grid_barrier();

    // pipelined loop: P-phase: PW1(t) | PW2(t-1) | PW3(t-2); G-phase: G2(t) | G1(t+1) | G3(t-1)
    for (int t = 0; t <= S_ + 1; t++) {
        float ts0 = (t < S_)                ? __ldg(&tspans[t])     : 0.f;
        float ts1 = (t >= 1 && t - 1 < S_)  ? __ldg(&tspans[t - 1]) : 0.f;
        float ts2 = (t >= 2)                ? __ldg(&tspans[t - 2]) : 0.f;

        // ---- P-phase ----
        if (t < S_)
            pointwise(g_P1, KS1_, NC1_, NHP1_, N1_, bg1, bh1, bfg1, bfh1, ts0, g_H1f,
                      g_Z1h, g_Z1l, Z1P_, INF_,
                      g_Z2h, g_Z2l, Z2P_, 0, nullptr, t);
        if (t >= 1 && t - 1 < S_)
            pointwise(g_P2, KS2_, NC2_, NHP2_, N2_, bg2, bh2, bfg2, bfh2, ts1, g_H2f,
                      g_Z2h, g_Z2l, Z2P_, N1_,
                      g_Z3h, g_Z3l, Z3P_, 0, nullptr, t - 1);
        if (t >= 2)
            pointwise(g_P3, KS3_, NC3_, NHP3_, N3_, bg3, bh3, bfg3, bfh3, ts2, g_H3f,
                      g_Z3h, g_Z3l, Z3P_, N2_,
                      nullptr, nullptr, 0, 0, out, t - 2);
        grid_barrier();

        // ---- G-phase ----
        bool h2 = (t < S_);
        bool h1 = (t + 1 < S_);
        bool h3 = (t >= 1 && t - 1 < S_);
        if (h1 && h2 && h3) {
            if (bid < I1_) {
                g1(bid, t + 1);
                if (bid < 104) g2(bid);
                else { int u = (bid - 104) * 2; g3(u); g3(u + 1); }
            } else if (bid < 143) {
                g2(104 + (bid - 117));
                int u = 26 + (bid - 117) * 4;
                g3(u); g3(u + 1); g3(u + 2); g3(u + 3);
            } else {
                int u = 130 + (bid - 143) * 3;
                g3(u);
                if (u + 1 < I3_) g3(u + 1);
                if (u + 2 < I3_) g3(u + 2);
            }
        } else {
            int n2 = h2 ? I2_ : 0, n1 = h1 ? I1_ : 0, n3 = h3 ? I3_ : 0;
            int tot = n2 + n1 + n3;
            for (int tl = bid; tl < tot; tl += NBLK_) {
                if (tl < n2) g2(tl);
                else if (tl < n2 + n1) g1(tl - n2, t + 1);
                else g3(tl - n2 - n1);
            }
        }
        grid_barrier();
    }

    // h_final = concat(h1,h2,h3) fp32
    float* hf = out + (size_t)B_ * S_ * N3_;
    for (int i = bid * blockDim.x + threadIdx.x; i < B_ * NU_; i += gridDim.x * blockDim.x) {
        int m = i / NU_, c = i - m * NU_;
        float v;
        if (c < N1_)            v = __ldcg(&g_H1f[m * N1_ + c]);
        else if (c < N1_ + N2_) v = __ldcg(&g_H2f[m * N2_ + (c - N1_)]);
        else                    v = __ldcg(&g_H3f[m * N3_ + (c - N1_ - N2_)]);
        hf[i] = v;
    }
}

// ---------------- launch ----------------
extern "C" void kernel_launch(void* const* d_in, const int* in_sizes, int n_in,
                              void* d_out, int out_size) {
    const float* x    = (const float*)d_in[0];
    const float* h0   = (const float*)d_in[1];
    const float* tsp  = (const float*)d_in[2];
    const float* Wg1  = (const float*)d_in[3];
    const float* Wh1  = (const float*)d_in[4];
    const float* Wfg1 = (const float*)d_in[5];
    const float* Wfh1 = (const float*)d_in[6];
    const float* bg1  = (const float*)d_in[7];
    const float* bh1  = (const float*)d_in[8];
    const float* bfg1 = (const float*)d_in[9];
    const float* bfh1 = (const float*)d_in[10];
    const float* msk1 = (const float*)d_in[11];
    const float* Wg2  = (const float*)d_in[12];
    const float* Wh2  = (const float*)d_in[13];
    const float* Wfg2 = (const float*)d_in[14];
    const float* Wfh2 = (const float*)d_in[15];
    const float* bg2  = (const float*)d_in[16];
    const float* bh2  = (const float*)d_in[17];
    const float* bfg2 = (const float*)d_in[18];
    const float* bfh2 = (const float*)d_in[19];
    const float* msk2 = (const float*)d_in[20];
    const float* Wg3  = (const float*)d_in[21];
    const float* Wh3  = (const float*)d_in[22];
    const float* Wfg3 = (const float*)d_in[23];
    const float* Wfh3 = (const float*)d_in[24];
    const float* bg3  = (const float*)d_in[25];
    const float* bh3  = (const float*)d_in[26];
    const float* bfg3 = (const float*)d_in[27];
    const float* bfh3 = (const float*)d_in[28];
    const float* msk3 = (const float*)d_in[29];
    float* out = (float*)d_out;

    cudaFuncSetAttribute(k_main, cudaFuncAttributeMaxDynamicSharedMemorySize, SMEM_RAW_);

    __half *w1, *w2, *w3;
    cudaGetSymbolAddress((void**)&w1, g_W1);
    cudaGetSymbolAddress((void**)&w2, g_W2);
    cudaGetSymbolAddress((void**)&w3, g_W3);

    k_prep<<<T1_ * C1_, NTHR_>>>(Wg1, Wh1, Wfg1, Wfh1, msk1, w1, N1_, K1_, NHP1_, C1_);
    k_prep<<<T2_ * C2_, NTHR_>>>(Wg2, Wh2, Wfg2, Wfh2, msk2, w2, N2_, K2_, NHP2_, C2_);
    k_prep<<<T3_ * C3_, NTHR_>>>(Wg3, Wh3, Wfg3, Wfh3, msk3, w3, N3_, K3_, NHP3_, C3_);
    k_xprep<<<(S_ * B_ * INF_ + NTHR_ - 1) / NTHR_, NTHR_>>>(x);
    k_init<<<256, NTHR_>>>(h0);
    k_main<<<NBLK_, NTHR_, SMEM_RAW_>>>(tsp, out,
                                        bg1, bh1, bfg1, bfh1,
                                        bg2, bh2, bfg2, bfh2,
                                        bg3, bh3, bfg3, bfh3);
    (void)in_sizes; (void)n_in; (void)out_size;
}

// round 17
// speedup vs baseline: 3.4781x; 1.1780x over previous
#include <cuda_runtime.h>
#include <cuda_fp16.h>
#include <mma.h>
#include <cmath>
#include <cstdint>

using namespace nvcuda;

// ---------------- problem constants ----------------
#define B_    64
#define S_    32
#define INF_  512
#define N1_   1229
#define N2_   819
#define N3_   512
#define NU_   2560
#define K1_   1741
#define K2_   2048
#define K3_   1331
#define NHP1_ 1248
#define NHP2_ 832
#define NHP3_ 512
#define NC1_  4992
#define NC2_  3328
#define NC3_  2048
#define T1_   39
#define T2_   26
#define T3_   16
#define C1_   28
#define C2_   32
#define C3_   21
#define Z1P_  1792
#define Z2P_  2048
#define Z3P_  1344
#define KS1_  3               // item counts: 117 / 130 / 144
#define KS2_  5
#define KS3_  9
#define NBLK_ 148
#define NTHR_ 256

#define I1_   (KS1_ * T1_)    // 117
#define I2_   (KS2_ * T2_)    // 130
#define I3_   (KS3_ * T3_)    // 144

// smem buffer layout (per buffer): A[128x72 fp16] B[64x72 fp16]
#define A_PL_   18432
#define B_PL_   9216
#define BUFSZ_  27648
#define SMEM_RAW_ (2 * BUFSZ_ + 256)

// ---------------- device scratch ----------------
__device__ __half g_W1[(size_t)T1_ * C1_ * 8192];
__device__ __half g_W2[(size_t)T2_ * C2_ * 8192];
__device__ __half g_W3[(size_t)T3_ * C3_ * 8192];
__device__ __half g_X[(size_t)S_ * B_ * INF_];
__device__ __half g_Z1[B_ * Z1P_];
__device__ __half g_Z2[B_ * Z2P_];
__device__ __half g_Z3[B_ * Z3P_];
__device__ float g_P1[(size_t)KS1_ * B_ * NC1_];
__device__ float g_P2[(size_t)KS2_ * B_ * NC2_];
__device__ float g_P3[(size_t)KS3_ * B_ * NC3_];
__device__ float g_H1f[B_ * N1_], g_H2f[B_ * N2_], g_H3f[B_ * N3_];
__device__ unsigned g_bar_cnt;
__device__ volatile unsigned g_bar_epoch;

// ---------------- async copy helpers ----------------
#define CP16(dst, src)  asm volatile("cp.async.ca.shared.global [%0], [%1], 16;" :: "r"(dst), "l"(src))
#define CPCOMMIT()      asm volatile("cp.async.commit_group;")
#define CPWAIT0()       asm volatile("cp.async.wait_group 0;")
#define CPWAIT1()       asm volatile("cp.async.wait_group 1;")

// ---------------- grid-wide barrier (tid0-only fences; cumulative-fence correct) ----------------
__device__ __forceinline__ void grid_barrier() {
    __syncthreads();
    if (threadIdx.x == 0) {
        __threadfence();
        unsigned e = g_bar_epoch;
        if (atomicAdd(&g_bar_cnt, 1u) == gridDim.x - 1u) {
            g_bar_cnt = 0u;
            __threadfence();
            g_bar_epoch = e + 1u;
        } else {
            while (g_bar_epoch == e) { }
        }
        __threadfence();
    }
    __syncthreads();
}

// ---------------- weight prep: mask, fp16, flat [tile][chunk][128][64] ----------------
__global__ void k_prep(const float* __restrict__ Wg, const float* __restrict__ Wh,
                       const float* __restrict__ Wfg, const float* __restrict__ Wfh,
                       const float* __restrict__ Msk,
                       __half* __restrict__ D,
                       int Nh, int K, int Nhp, int nchunks) {
    int blk = blockIdx.x;
    int tile = blk / nchunks, chunk = blk - tile * nchunks;
    size_t base = (size_t)blk * 8192;
    for (int e = threadIdx.x; e < 8192; e += blockDim.x) {
        int row = e >> 6, col = e & 63;
        int nc = tile * 128 + row;
        int hd = nc / Nhp, n = nc - hd * Nhp;
        int kk = chunk * 64 + col;
        float v = 0.f;
        if (n < Nh && kk < K) {
            const float* W = (hd == 0) ? Wg : (hd == 1) ? Wh : (hd == 2) ? Wfg : Wfh;
            v = W[(size_t)n * K + kk] * Msk[(size_t)n * K + kk];
        }
        D[base + e] = __float2half_rn(v);
    }
}

// ---------------- x to fp16, [t][batch][512] ----------------
__global__ void k_xprep(const float* __restrict__ x) {
    int i = blockIdx.x * blockDim.x + threadIdx.x;
    if (i < S_ * B_ * INF_) {
        int f = i & (INF_ - 1);
        int r = i >> 9;
        int t = r / B_, b = r - t * B_;
        g_X[i] = __float2half_rn(x[((size_t)b * S_ + t) * INF_ + f]);
    }
}

// ---------------- init: scatter h0 into fp32 + fp16 planes, zero pad cols ----------------
__global__ void k_init(const float* __restrict__ h0) {
    int stride = gridDim.x * blockDim.x;
    for (int i = blockIdx.x * blockDim.x + threadIdx.x; i < B_ * NU_; i += stride) {
        int m = i / NU_, c = i - m * NU_;
        float v = h0[i];
        __half hv = __float2half_rn(v);
        if (c < N1_) {
            g_H1f[m * N1_ + c] = v;
            g_Z1[m * Z1P_ + INF_ + c] = hv;
        } else if (c < N1_ + N2_) {
            int cc = c - N1_;
            g_H2f[m * N2_ + cc] = v;
            g_Z2[m * Z2P_ + N1_ + cc] = hv;
        } else {
            int cc = c - N1_ - N2_;
            g_H3f[m * N3_ + cc] = v;
            g_Z3[m * Z3P_ + N2_ + cc] = hv;
        }
    }
    for (int i = blockIdx.x * blockDim.x + threadIdx.x; i < B_ * (Z1P_ - K1_); i += stride) {
        int m = i / (Z1P_ - K1_), c = K1_ + (i - m * (Z1P_ - K1_));
        g_Z1[m * Z1P_ + c] = __float2half_rn(0.f);
    }
    for (int i = blockIdx.x * blockDim.x + threadIdx.x; i < B_ * (Z3P_ - K3_); i += stride) {
        int m = i / (Z3P_ - K3_), c = K3_ + (i - m * (Z3P_ - K3_));
        g_Z3[m * Z3P_ + c] = __float2half_rn(0.f);
    }
}

// ---------------- chunk staging into smem via cp.async ----------------
__device__ __forceinline__ void stage_chunk(uint32_t sb,
        const __half* __restrict__ W, size_t wbase,
        const __half* __restrict__ z, int zstride, int colbase) {
    int tid = threadIdx.x;
#pragma unroll
    for (int i = 0; i < 4; i++) {                 // A: 16KB (128 rows x 128B)
        int e = tid + i * 256;
        int r = e >> 3, u = e & 7;
        const char* g = (const char*)(W + wbase) + r * 128 + u * 16;
        CP16(sb + r * 144 + u * 16, g);
    }
    {                                             // B: 8KB (64 rows x 128B)
        int e = tid + 512 * 0;                    // two rounds of 256
#pragma unroll
        for (int i = 0; i < 2; i++) {
            e = tid + i * 256;
            int r = e >> 3, u = e & 7;
            const char* g = (const char*)(z + (size_t)r * zstride + colbase) + u * 16;
            CP16(sb + A_PL_ + r * 144 + u * 16, g);
        }
    }
}

// ---------------- one GEMM tile (wmma fp16 single-pass, reg accum) ----------------
typedef wmma::fragment<wmma::matrix_a, 16, 16, 16, __half, wmma::row_major> FragA;
typedef wmma::fragment<wmma::matrix_b, 16, 16, 16, __half, wmma::col_major> FragB;
typedef wmma::fragment<wmma::accumulator, 16, 16, 16, float> FragC;

__device__ void gemm_tile(char* smc, uint32_t smb,
        const __half* __restrict__ W,
        int nchunks, int ksplit, int ks, int nt,
        const __half* __restrict__ xz, int xstride, int xchunks,
        const __half* __restrict__ z, int zstride,
        float* __restrict__ P, int NC) {
    int cb = nchunks * ks / ksplit, ce = nchunks * (ks + 1) / ksplit;
    int wid = threadIdx.x >> 5;
    int m0 = (wid & 3) * 32, n0 = (wid >> 2) * 32;

    FragC acc[2][2];
#pragma unroll
    for (int mi = 0; mi < 2; mi++)
#pragma unroll
        for (int ni = 0; ni < 2; ni++) wmma::fill_fragment(acc[mi][ni], 0.f);

    {
        bool ux = cb < xchunks;
        stage_chunk(smb, W, (size_t)(nt * nchunks + cb) * 8192,
                    ux ? xz : z, ux ? xstride : zstride, cb * 64);
        CPCOMMIT();
    }
    for (int c = cb; c < ce; c++) {
        uint32_t b = (uint32_t)(c - cb) & 1u;
        if (c + 1 < ce) {
            int cn = c + 1;
            bool ux = cn < xchunks;
            stage_chunk(smb + (b ^ 1u) * BUFSZ_, W, (size_t)(nt * nchunks + cn) * 8192,
                        ux ? xz : z, ux ? xstride : zstride, cn * 64);
            CPCOMMIT();
            CPWAIT1();
        } else {
            CPWAIT0();
        }
        __syncthreads();
        const __half* A_p = (const __half*)(smc + b * BUFSZ_);
        const __half* B_p = (const __half*)(smc + b * BUFSZ_ + A_PL_);
#pragma unroll
        for (int k = 0; k < 4; k++) {
            FragA ah[2];
            FragB bh[2];
            wmma::load_matrix_sync(ah[0], A_p + (m0 +  0) * 72 + k * 16, 72);
            wmma::load_matrix_sync(ah[1], A_p + (m0 + 16) * 72 + k * 16, 72);
            wmma::load_matrix_sync(bh[0], B_p + (n0 +  0) * 72 + k * 16, 72);
            wmma::load_matrix_sync(bh[1], B_p + (n0 + 16) * 72 + k * 16, 72);
#pragma unroll
            for (int mi = 0; mi < 2; mi++)
#pragma unroll
                for (int ni = 0; ni < 2; ni++)
                    wmma::mma_sync(acc[mi][ni], ah[mi], bh[ni], acc[mi][ni]);
        }
        __syncthreads();
    }
#pragma unroll
    for (int mi = 0; mi < 2; mi++)
#pragma unroll
        for (int ni = 0; ni < 2; ni++) {
            float* pp = P + (size_t)(ks * 64 + n0 + ni * 16) * NC + nt * 128 + m0 + mi * 16;
            wmma::store_matrix_sync(pp, acc[mi][ni], NC, wmma::mem_col_major);
        }
}

// ---------------- fused reduce + bias + CfC pointwise ----------------
__device__ void pointwise(const float* __restrict__ P, int ksplit, int NC, int Nhp, int Nh,
                          const float* __restrict__ bg, const float* __restrict__ bh,
                          const float* __restrict__ bfg, const float* __restrict__ bfh,
                          float ts, float* __restrict__ Hf,
                          __half* __restrict__ d0, int d0s, int d0off,
                          __half* __restrict__ d1, int d1s, int d1off,
                          float* __restrict__ y, int t) {
    int tot = B_ * Nh;
    for (int idx = blockIdx.x * blockDim.x + threadIdx.x; idx < tot; idx += gridDim.x * blockDim.x) {
        int m = idx / Nh, n = idx - m * Nh;
        float s0 = 0.f, s1 = 0.f, s2 = 0.f, s3 = 0.f;
        for (int ks = 0; ks < ksplit; ks++) {
            const float* pb = P + (size_t)(ks * 64 + m) * NC + n;
            s0 += __ldcg(pb);
            s1 += __ldcg(pb + Nhp);
            s2 += __ldcg(pb + 2 * Nhp);
            s3 += __ldcg(pb + 3 * Nhp);
        }
        s0 += __ldg(&bg[n]); s1 += __ldg(&bh[n]); s2 += __ldg(&bfg[n]); s3 += __ldg(&bfh[n]);
        float gv = tanhf(s0), hv = tanhf(s1);
        float gate = 1.f / (1.f + __expf(-(s2 + ts * s3)));
        float ov = gv * (1.f - gate) + hv * gate;
        Hf[idx] = ov;
        __half hq = __float2half_rn(ov);
        d0[(size_t)m * d0s + d0off + n] = hq;
        if (d1) d1[(size_t)m * d1s + d1off + n] = hq;
        if (y) y[((size_t)m * S_ + t) * N3_ + n] = ov;
    }
}

// ---------------- persistent time-loop kernel (software-pipelined cells) ----------------
__global__ __launch_bounds__(NTHR_, 1)
void k_main(const float* __restrict__ tspans, float* __restrict__ out,
            const float* __restrict__ bg1, const float* __restrict__ bh1,
            const float* __restrict__ bfg1, const float* __restrict__ bfh1,
            const float* __restrict__ bg2, const float* __restrict__ bh2,
            const float* __restrict__ bfg2, const float* __restrict__ bfh2,
            const float* __restrict__ bg3, const float* __restrict__ bh3,
            const float* __restrict__ bfg3, const float* __restrict__ bfh3) {
    extern __shared__ char smraw[];
    uint32_t raw32;
    asm("{ .reg .u64 t; cvta.to.shared.u64 t, %1; cvt.u32.u64 %0, t; }" : "=r"(raw32) : "l"(smraw));
    uint32_t smb = (raw32 + 127u) & ~127u;
    char* smc = smraw + (smb - raw32);
    int bid = blockIdx.x;

    auto g1 = [&](int tile, int t) {
        int ks = tile / T1_, nt = tile - ks * T1_;
        gemm_tile(smc, smb, g_W1, C1_, KS1_, ks, nt,
                  g_X + (size_t)t * B_ * INF_, INF_, 8,
                  g_Z1, Z1P_, g_P1, NC1_);
    };
    auto g2 = [&](int tile) {
        int ks = tile / T2_, nt = tile - ks * T2_;
        gemm_tile(smc, smb, g_W2, C2_, KS2_, ks, nt,
                  (const __half*)nullptr, 0, 0,
                  g_Z2, Z2P_, g_P2, NC2_);
    };
    auto g3 = [&](int tile) {
        int ks = tile / T3_, nt = tile - ks * T3_;
        gemm_tile(smc, smb, g_W3, C3_, KS3_, ks, nt,
                  (const __half*)nullptr, 0, 0,
                  g_Z3, Z3P_, g_P3, NC3_);
    };

    // prime: GEMM1(0)
    for (int tl = bid; tl < I1_; tl += NBLK_) g1(tl, 0);
    grid_barrier();

    // pipelined loop: P-phase: PW1(t) | PW2(t-1) | PW3(t-2); G-phase: G2(t) | G1(t+1) | G3(t-1)
    for (int t = 0; t <= S_ + 1; t++) {
        float ts0 = (t < S_)                ? __ldg(&tspans[t])     : 0.f;
        float ts1 = (t >= 1 && t - 1 < S_)  ? __ldg(&tspans[t - 1]) : 0.f;
        float ts2 = (t >= 2)                ? __ldg(&tspans[t - 2]) : 0.f;

        // ---- P-phase ----
        if (t < S_)
            pointwise(g_P1, KS1_, NC1_, NHP1_, N1_, bg1, bh1, bfg1, bfh1, ts0, g_H1f,
                      g_Z1, Z1P_, INF_,
                      g_Z2, Z2P_, 0, nullptr, t);
        if (t >= 1 && t - 1 < S_)
            pointwise(g_P2, KS2_, NC2_, NHP2_, N2_, bg2, bh2, bfg2, bfh2, ts1, g_H2f,
                      g_Z2, Z2P_, N1_,
                      g_Z3, Z3P_, 0, nullptr, t - 1);
        if (t >= 2)
            pointwise(g_P3, KS3_, NC3_, NHP3_, N3_, bg3, bh3, bfg3, bfh3, ts2, g_H3f,
                      g_Z3, Z3P_, N2_,
                      nullptr, 0, 0, out, t - 2);
        grid_barrier();

        // ---- G-phase ----
        bool h2 = (t < S_);
        bool h1 = (t + 1 < S_);
        bool h3 = (t >= 1 && t - 1 < S_);
        if (h1 && h2 && h3) {
            if (bid < I1_) {
                g1(bid, t + 1);
                if (bid < 104) g2(bid);
                else { int u = (bid - 104) * 2; g3(u); g3(u + 1); }
            } else if (bid < 143) {
                g2(104 + (bid - 117));
                int u = 26 + (bid - 117) * 4;
                g3(u); g3(u + 1); g3(u + 2); g3(u + 3);
            } else {
                int u = 130 + (bid - 143) * 3;
                g3(u);
                if (u + 1 < I3_) g3(u + 1);
                if (u + 2 < I3_) g3(u + 2);
            }
        } else {
            int n2 = h2 ? I2_ : 0, n1 = h1 ? I1_ : 0, n3 = h3 ? I3_ : 0;
            int tot = n2 + n1 + n3;
            for (int tl = bid; tl < tot; tl += NBLK_) {
                if (tl < n2) g2(tl);
                else if (tl < n2 + n1) g1(tl - n2, t + 1);
                else g3(tl - n2 - n1);
            }
        }
        grid_barrier();
    }

    // h_final = concat(h1,h2,h3) fp32
    float* hf = out + (size_t)B_ * S_ * N3_;
    for (int i = bid * blockDim.x + threadIdx.x; i < B_ * NU_; i += gridDim.x * blockDim.x) {
        int m = i / NU_, c = i - m * NU_;
        float v;
        if (c < N1_)            v = __ldcg(&g_H1f[m * N1_ + c]);
        else if (c < N1_ + N2_) v = __ldcg(&g_H2f[m * N2_ + (c - N1_)]);
        else                    v = __ldcg(&g_H3f[m * N3_ + (c - N1_ - N2_)]);
        hf[i] = v;
    }
}

// ---------------- launch ----------------
extern "C" void kernel_launch(void* const* d_in, const int* in_sizes, int n_in,
                              void* d_out, int out_size) {
    const float* x    = (const float*)d_in[0];
    const float* h0   = (const float*)d_in[1];
    const float* tsp  = (const float*)d_in[2];
    const float* Wg1  = (const float*)d_in[3];
    const float* Wh1  = (const float*)d_in[4];
    const float* Wfg1 = (const float*)d_in[5];
    const float* Wfh1 = (const float*)d_in[6];
    const float* bg1  = (const float*)d_in[7];
    const float* bh1  = (const float*)d_in[8];
    const float* bfg1 = (const float*)d_in[9];
    const float* bfh1 = (const float*)d_in[10];
    const float* msk1 = (const float*)d_in[11];
    const float* Wg2  = (const float*)d_in[12];
    const float* Wh2  = (const float*)d_in[13];
    const float* Wfg2 = (const float*)d_in[14];
    const float* Wfh2 = (const float*)d_in[15];
    const float* bg2  = (const float*)d_in[16];
    const float* bh2  = (const float*)d_in[17];
    const float* bfg2 = (const float*)d_in[18];
    const float* bfh2 = (const float*)d_in[19];
    const float* msk2 = (const float*)d_in[20];
    const float* Wg3  = (const float*)d_in[21];
    const float* Wh3  = (const float*)d_in[22];
    const float* Wfg3 = (const float*)d_in[23];
    const float* Wfh3 = (const float*)d_in[24];
    const float* bg3  = (const float*)d_in[25];
    const float* bh3  = (const float*)d_in[26];
    const float* bfg3 = (const float*)d_in[27];
    const float* bfh3 = (const float*)d_in[28];
    const float* msk3 = (const float*)d_in[29];
    float* out = (float*)d_out;

    cudaFuncSetAttribute(k_main, cudaFuncAttributeMaxDynamicSharedMemorySize, SMEM_RAW_);

    __half *w1, *w2, *w3;
    cudaGetSymbolAddress((void**)&w1, g_W1);
    cudaGetSymbolAddress((void**)&w2, g_W2);
    cudaGetSymbolAddress((void**)&w3, g_W3);

    k_prep<<<T1_ * C1_, NTHR_>>>(Wg1, Wh1, Wfg1, Wfh1, msk1, w1, N1_, K1_, NHP1_, C1_);
    k_prep<<<T2_ * C2_, NTHR_>>>(Wg2, Wh2, Wfg2, Wfh2, msk2, w2, N2_, K2_, NHP2_, C2_);
    k_prep<<<T3_ * C3_, NTHR_>>>(Wg3, Wh3, Wfg3, Wfh3, msk3, w3, N3_, K3_, NHP3_, C3_);
    k_xprep<<<(S_ * B_ * INF_ + NTHR_ - 1) / NTHR_, NTHR_>>>(x);
    k_init<<<256, NTHR_>>>(h0);
    k_main<<<NBLK_, NTHR_, SMEM_RAW_>>>(tsp, out,
                                        bg1, bh1, bfg1, bfh1,
                                        bg2, bh2, bfg2, bfh2,
                                        bg3, bh3, bfg3, bfh3);
    (void)in_sizes; (void)n_in; (void)out_size;
}